// round 1
// baseline (speedup 1.0000x reference)
#include <cuda_runtime.h>
#include <stdint.h>

#define BB 8
#define SS 2047
#define RT 1162
#define ROWS (BB * SS)

// Prefix state per (b, j): words 0..4 = instrument-present bitset (129 bits),
// word 5 = key_sign: 0x80000000|last_idx (flag = has_ks), 0 if none,
// word 6 = time_sign: same encoding, word 7 = tempo last_idx (plain, default 0).
__device__ uint32_t g_prefix[ROWS * 8];

__constant__ int c_num[12] = {1, 2, 3, 4, 5, 6, 7, 8, 9, 10, 12, 16};

__global__ __launch_bounds__(256) void prefix_kernel(const int* __restrict__ song) {
    int b = blockIdx.x;
    int tid = threadIdx.x;
    const int* sb = song + b * SS * 11;

    uint32_t loc[8] = {0, 0, 0, 0, 0, 0, 0, 0};
    int j0 = tid * 8;
#pragma unroll
    for (int k = 0; k < 8; ++k) {
        int j = j0 + k;
        if (j < SS) {
            int ty = sb[j * 11];
            if (ty == 1) {
                int v = sb[j * 11 + 6];
                loc[v >> 5] |= 1u << (v & 31);
            } else if (ty == 4) {
                loc[5] = 0x80000000u | (uint32_t)j;
            } else if (ty == 5) {
                loc[6] = 0x80000000u | (uint32_t)j;
            } else if (ty == 6) {
                loc[7] = (uint32_t)j;
            }
        }
    }

    __shared__ uint32_t sm[8][256];
#pragma unroll
    for (int w = 0; w < 8; ++w) sm[w][tid] = loc[w];
    __syncthreads();

    // Hillis-Steele inclusive scan across 256 threads.
    for (int d = 1; d < 256; d <<= 1) {
        uint32_t v[8];
        if (tid >= d) {
#pragma unroll
            for (int w = 0; w < 8; ++w) {
                uint32_t a = sm[w][tid];
                uint32_t x = sm[w][tid - d];
                v[w] = (w < 5) ? (a | x) : (a > x ? a : x);
            }
        }
        __syncthreads();
        if (tid >= d) {
#pragma unroll
            for (int w = 0; w < 8; ++w) sm[w][tid] = v[w];
        }
        __syncthreads();
    }

    uint32_t run[8];
#pragma unroll
    for (int w = 0; w < 8; ++w) run[w] = (tid > 0) ? sm[w][tid - 1] : 0u;

    // Pass 2: apply elements, emit inclusive prefix per position.
#pragma unroll
    for (int k = 0; k < 8; ++k) {
        int j = j0 + k;
        if (j < SS) {
            int ty = sb[j * 11];
            if (ty == 1) {
                int v = sb[j * 11 + 6];
                run[v >> 5] |= 1u << (v & 31);
            } else if (ty == 4) {
                run[5] = 0x80000000u | (uint32_t)j;  // j >= any earlier idx
            } else if (ty == 5) {
                run[6] = 0x80000000u | (uint32_t)j;
            } else if (ty == 6) {
                run[7] = (uint32_t)j;
            }
            uint32_t* P = &g_prefix[(size_t)(b * SS + j) * 8];
#pragma unroll
            for (int w = 0; w < 8; ++w) P[w] = run[w];
        }
    }
}

__device__ __forceinline__ bool mvalid(int c, int mth, int blo, int bhi, int pth,
                                       int imode, int kmode, int kval,
                                       int tsm, int tsv, int tpm, int tpv,
                                       const uint32_t* __restrict__ bits) {
    if (c < 256) return c >= mth;                               // measure
    if (c < 272) { int cb = c - 256; return cb >= blo && cb < bhi; }  // beat
    if (c < 400) return (c - 272) >= pth;                       // position
    if (c < 784) return true;                                   // duration + pitch
    if (c < 913) {                                              // instrument
        if (imode == 0) return true;
        int ci = c - 784;
        bool pres = (bits[ci >> 5] >> (ci & 31)) & 1u;
        return (imode == 1) ? pres : !pres;
    }
    if (c < 1041) return true;                                  // velocity
    if (c < 1065) {                                             // key_sign
        if (kmode == 0) return true;
        int ck = c - 1041;
        return (kmode == 1) ? (ck == kval) : (ck != kval);
    }
    if (c < 1113) {                                             // time_sign
        if (tsm == 0) return true;
        int ct = c - 1065;
        return (tsm == 1) ? (ct == tsv) : (ct != tsv);
    }
    // tempo
    if (tpm == 0) return true;
    int cp = c - 1113;
    return (tpm == 1) ? (cp == tpv) : (cp != tpv);
}

__global__ __launch_bounds__(256) void mask_kernel(const int* __restrict__ song,
                                                   const int* __restrict__ chosen,
                                                   const float* __restrict__ scores,
                                                   float* __restrict__ out) {
    int row = blockIdx.x;
    int b = row / SS;
    int i = row - b * SS;
    int tid = threadIdx.x;
    const float* srow = scores + (size_t)row * RT;
    float* orow = out + (size_t)row * RT;

    __shared__ float s_wval[8];
    __shared__ int s_widx[8];
    __shared__ uint32_t s_bits[5];
    __shared__ int s_raw[6];   // last_ks, has_ks, last_ts, has_ts, last_tp, max_beat
    __shared__ int s_par[11];
    __shared__ int s_predb;

    int jj = (i + 1 < SS) ? i + 1 : SS - 1;
    const uint32_t* P = &g_prefix[(size_t)(b * SS + jj) * 8];

    // --- scalar prep in warp 1 (parallel with the argmax below) ---
    if (tid >= 32 && tid < 37) s_bits[tid - 32] = P[tid - 32];
    if (tid == 37) {
        uint32_t w = P[5];
        int idx = (int)(w & 0x7fffffffu);
        s_raw[0] = song[(size_t)(b * SS + idx) * 11 + 8];
        s_raw[1] = (int)(w >> 31);
    }
    if (tid == 38) {
        uint32_t w = P[6];
        int idx = (int)(w & 0x7fffffffu);
        int lts = song[(size_t)(b * SS + idx) * 11 + 9];
        s_raw[2] = lts;
        s_raw[3] = (int)(w >> 31);
        s_raw[5] = c_num[lts % 12];
    }
    if (tid == 39) {
        uint32_t w = P[7];
        s_raw[4] = song[(size_t)(b * SS + (int)w) * 11 + 10];
    }

    // --- argmax over scores[0:256] (first-index tiebreak, matches jnp.argmax) ---
    {
        float v = srow[tid];
        int idx = tid;
#pragma unroll
        for (int d = 16; d; d >>= 1) {
            float ov = __shfl_down_sync(0xffffffffu, v, d);
            int oi = __shfl_down_sync(0xffffffffu, idx, d);
            if (ov > v || (ov == v && oi < idx)) { v = ov; idx = oi; }
        }
        if ((tid & 31) == 0) { s_wval[tid >> 5] = v; s_widx[tid >> 5] = idx; }
    }

    // --- pred_b over scores[256:272] in warp 2 lanes 0..15 ---
    if (tid >= 64 && tid < 80) {
        int l = tid - 64;
        float bv = srow[256 + l];
        int bi = l;
#pragma unroll
        for (int d = 8; d; d >>= 1) {
            float ov = __shfl_down_sync(0xffffu, bv, d, 16);
            int oi = __shfl_down_sync(0xffffu, bi, d, 16);
            if (ov > bv || (ov == bv && oi < bi)) { bv = ov; bi = oi; }
        }
        if (l == 0) s_predb = bi;
    }
    __syncthreads();

    if (tid == 0) {
        float bv = s_wval[0];
        int bi = s_widx[0];
#pragma unroll
        for (int w = 1; w < 8; ++w)
            if (s_wval[w] > bv || (s_wval[w] == bv && s_widx[w] < bi)) {
                bv = s_wval[w]; bi = s_widx[w];
            }
        int pred_m = bi;
        int pred_b = s_predb;

        const int* srowi = song + (size_t)(b * SS + i) * 11;
        int sm1 = srowi[1], sb2 = srowi[2], sp3 = srowi[3];
        int t = chosen[row];

        bool c1 = (pred_m == sm1);
        int min_beat = c1 ? sb2 : 0;
        bool c2 = c1 && (pred_b == min_beat);
        int min_pos = c2 ? sp3 : 0;
        int min_m46 = (sb2 == 0 && sp3 == 0) ? sm1 : sm1 + 1;

        bool has_inst = (s_bits[0] | s_bits[1] | s_bits[2] | s_bits[3] | s_bits[4]) != 0;
        int last_ks = s_raw[0];
        bool has_ks = s_raw[1] != 0;
        int last_ts = s_raw[2];
        bool has_ts = s_raw[3] != 0;
        int last_tp = s_raw[4];
        int max_beat = s_raw[5];

        bool is3 = (t == 3);
        s_par[0]  = is3 ? sm1 : ((t >= 4 && t <= 6) ? min_m46 : 0);   // measure threshold
        s_par[1]  = is3 ? min_beat : 0;                                // beat lo
        s_par[2]  = is3 ? max_beat : 16;                               // beat hi
        s_par[3]  = is3 ? min_pos : 0;                                 // position threshold
        s_par[4]  = is3 ? 1 : ((t == 1 && has_inst) ? 2 : 0);          // instrument mode
        s_par[5]  = is3 ? 1 : ((t == 4 && has_ks) ? 2 : 0);            // key_sign mode
        s_par[6]  = last_ks;
        s_par[7]  = is3 ? 1 : ((t == 5 && has_ts) ? 2 : 0);            // time_sign mode
        s_par[8]  = last_ts;
        s_par[9]  = is3 ? 1 : ((t == 6) ? 2 : 0);                      // tempo mode
        s_par[10] = last_tp;
    }
    __syncthreads();

    int mth = s_par[0], blo = s_par[1], bhi = s_par[2], pth = s_par[3];
    int imode = s_par[4], kmode = s_par[5], kval = s_par[6];
    int tsm = s_par[7], tsv = s_par[8], tpm = s_par[9], tpv = s_par[10];

    const float2* s2 = (const float2*)srow;   // row stride 4648 B: 8B-aligned
    float2* o2 = (float2*)orow;
#pragma unroll 2
    for (int p = tid; p < RT / 2; p += 256) {
        float2 x = s2[p];
        int c = 2 * p;
        if (!mvalid(c, mth, blo, bhi, pth, imode, kmode, kval, tsm, tsv, tpm, tpv, s_bits))
            x.x = -1e9f;
        if (!mvalid(c + 1, mth, blo, bhi, pth, imode, kmode, kval, tsm, tsv, tpm, tpv, s_bits))
            x.y = -1e9f;
        o2[p] = x;
    }
}

extern "C" void kernel_launch(void* const* d_in, const int* in_sizes, int n_in,
                              void* d_out, int out_size) {
    const int* song = (const int*)d_in[0];
    const int* chosen = (const int*)d_in[1];
    const float* scores = (const float*)d_in[2];
    float* out = (float*)d_out;

    prefix_kernel<<<BB, 256>>>(song);
    mask_kernel<<<ROWS, 256>>>(song, chosen, scores, out);
}

// round 2
// speedup vs baseline: 1.3852x; 1.3852x over previous
#include <cuda_runtime.h>
#include <stdint.h>

#define BB 8
#define SS 2047
#define RT 1162
#define ROWS (BB * SS)
#define NEGF (-1e9f)

// Prefix state per (b, j): words 0..4 = instrument-present bitset (129 bits),
// word 5 = key_sign: 0x80000000|last_idx, word 6 = time_sign: same,
// word 7 = tempo last_idx (plain, default 0 matches jnp.argmax-of-zeros).
__device__ uint32_t g_prefix[ROWS * 8];
// Per-row params: [0..4]=inst bits, [5]=measure_th, [6]=beat_lo, [7]=beat_hi,
// [8]=pos_th, [9]=inst_mode, [10]=ks_mode, [11]=ks_val, [12]=ts_mode,
// [13]=ts_val, [14]=tp_mode, [15]=tp_val.
__device__ int g_par[(size_t)ROWS * 16];

__constant__ int c_num[12] = {1, 2, 3, 4, 5, 6, 7, 8, 9, 10, 12, 16};

__global__ __launch_bounds__(256) void prefix_kernel(const int* __restrict__ song) {
    int b = blockIdx.x;
    int tid = threadIdx.x;
    const int* sb = song + b * SS * 11;

    uint32_t loc[8] = {0, 0, 0, 0, 0, 0, 0, 0};
    int j0 = tid * 8;
#pragma unroll
    for (int k = 0; k < 8; ++k) {
        int j = j0 + k;
        if (j < SS) {
            int ty = sb[j * 11];
            if (ty == 1) {
                int v = sb[j * 11 + 6];
                loc[v >> 5] |= 1u << (v & 31);
            } else if (ty == 4) {
                loc[5] = 0x80000000u | (uint32_t)j;
            } else if (ty == 5) {
                loc[6] = 0x80000000u | (uint32_t)j;
            } else if (ty == 6) {
                loc[7] = (uint32_t)j;
            }
        }
    }

    __shared__ uint32_t sm[8][256];
#pragma unroll
    for (int w = 0; w < 8; ++w) sm[w][tid] = loc[w];
    __syncthreads();

    for (int d = 1; d < 256; d <<= 1) {
        uint32_t v[8];
        if (tid >= d) {
#pragma unroll
            for (int w = 0; w < 8; ++w) {
                uint32_t a = sm[w][tid];
                uint32_t x = sm[w][tid - d];
                v[w] = (w < 5) ? (a | x) : (a > x ? a : x);
            }
        }
        __syncthreads();
        if (tid >= d) {
#pragma unroll
            for (int w = 0; w < 8; ++w) sm[w][tid] = v[w];
        }
        __syncthreads();
    }

    uint32_t run[8];
#pragma unroll
    for (int w = 0; w < 8; ++w) run[w] = (tid > 0) ? sm[w][tid - 1] : 0u;

#pragma unroll
    for (int k = 0; k < 8; ++k) {
        int j = j0 + k;
        if (j < SS) {
            int ty = sb[j * 11];
            if (ty == 1) {
                int v = sb[j * 11 + 6];
                run[v >> 5] |= 1u << (v & 31);
            } else if (ty == 4) {
                run[5] = 0x80000000u | (uint32_t)j;
            } else if (ty == 5) {
                run[6] = 0x80000000u | (uint32_t)j;
            } else if (ty == 6) {
                run[7] = (uint32_t)j;
            }
            uint32_t* P = &g_prefix[(size_t)(b * SS + j) * 8];
#pragma unroll
            for (int w = 0; w < 8; ++w) P[w] = run[w];
        }
    }
}

// One warp per row: argmax + scalar param derivation.
__global__ __launch_bounds__(256) void params_kernel(const int* __restrict__ song,
                                                     const int* __restrict__ chosen,
                                                     const float* __restrict__ scores) {
    int warp = threadIdx.x >> 5;
    int lane = threadIdx.x & 31;
    int row = blockIdx.x * 8 + warp;   // grid = SS blocks = 2047*8 = 16376 rows exactly
    int b = row / SS;
    int i = row - b * SS;
    const float* srow = scores + (size_t)row * RT;

    // argmax over scores[0:256], first-index tiebreak (matches jnp.argmax)
    float bv = srow[lane];
    int bi = lane;
#pragma unroll
    for (int k = 1; k < 8; ++k) {
        float v = srow[lane + 32 * k];
        if (v > bv) { bv = v; bi = lane + 32 * k; }
    }
#pragma unroll
    for (int d = 16; d; d >>= 1) {
        float ov = __shfl_down_sync(0xffffffffu, bv, d);
        int oi = __shfl_down_sync(0xffffffffu, bi, d);
        if (ov > bv || (ov == bv && oi < bi)) { bv = ov; bi = oi; }
    }
    int pred_m = __shfl_sync(0xffffffffu, bi, 0);

    // pred_b over scores[256:272]
    float bb = (lane < 16) ? srow[256 + lane] : -__int_as_float(0x7f800000);
    int bj = lane;
#pragma unroll
    for (int d = 8; d; d >>= 1) {
        float ov = __shfl_down_sync(0xffffffffu, bb, d);
        int oj = __shfl_down_sync(0xffffffffu, bj, d);
        if (ov > bb || (ov == bb && oj < bj)) { bb = ov; bj = oj; }
    }
    int pred_b = __shfl_sync(0xffffffffu, bj, 0);

    if (lane == 0) {
        int jj = (i + 1 < SS) ? i + 1 : SS - 1;
        const uint32_t* P = &g_prefix[(size_t)(b * SS + jj) * 8];
        uint32_t w0 = P[0], w1 = P[1], w2 = P[2], w3 = P[3], w4 = P[4];
        uint32_t wk = P[5], wt = P[6], wp = P[7];
        int ksidx = (int)(wk & 0x7fffffffu);
        int tsidx = (int)(wt & 0x7fffffffu);
        bool has_ks = (wk >> 31) != 0;
        bool has_ts = (wt >> 31) != 0;
        int last_ks = song[(size_t)(b * SS + ksidx) * 11 + 8];
        int last_ts = song[(size_t)(b * SS + tsidx) * 11 + 9];
        int last_tp = song[(size_t)(b * SS + (int)wp) * 11 + 10];
        int max_beat = c_num[last_ts % 12];

        const int* si = song + (size_t)row * 11;
        int sm1 = si[1], sb2 = si[2], sp3 = si[3];
        int t = chosen[row];

        bool c1 = (pred_m == sm1);
        int min_beat = c1 ? sb2 : 0;
        bool c2 = c1 && (pred_b == min_beat);
        int min_pos = c2 ? sp3 : 0;
        int min_m46 = (sb2 == 0 && sp3 == 0) ? sm1 : sm1 + 1;
        bool has_inst = (w0 | w1 | w2 | w3 | w4) != 0;
        bool is3 = (t == 3);

        int* pr = &g_par[(size_t)row * 16];
        pr[0] = (int)w0; pr[1] = (int)w1; pr[2] = (int)w2; pr[3] = (int)w3; pr[4] = (int)w4;
        pr[5] = is3 ? sm1 : ((t >= 4 && t <= 6) ? min_m46 : 0);
        pr[6] = is3 ? min_beat : 0;
        pr[7] = is3 ? max_beat : 16;
        pr[8] = is3 ? min_pos : 0;
        pr[9] = is3 ? 1 : ((t == 1 && has_inst) ? 2 : 0);
        pr[10] = is3 ? 1 : ((t == 4 && has_ks) ? 2 : 0);
        pr[11] = last_ks;
        pr[12] = is3 ? 1 : ((t == 5 && has_ts) ? 2 : 0);
        pr[13] = last_ts;
        pr[14] = is3 ? 1 : ((t == 6) ? 2 : 0);
        pr[15] = last_tp;
    }
}

// Block per row: branch-free float4 copy, then sparse -1e9 overwrites.
__global__ __launch_bounds__(256) void apply_kernel(const float* __restrict__ scores,
                                                    float* __restrict__ out) {
    int row = blockIdx.x;
    int tid = threadIdx.x;
    const float* srow = scores + (size_t)row * RT;
    float* orow = out + (size_t)row * RT;

    __shared__ int sp[16];
    if (tid < 16) sp[tid] = g_par[(size_t)row * 16 + tid];

    // Row byte offset = row*4648; 16B-aligned iff row even.
    if ((row & 1) == 0) {
        const float4* s4 = (const float4*)srow;
        float4* o4 = (float4*)orow;
        o4[tid] = s4[tid];
        if (tid < 34) o4[256 + tid] = s4[256 + tid];        // 290 float4 = floats 0..1159
        if (tid == 255) {                                    // tail: floats 1160,1161
            float2 t2 = *(const float2*)(srow + 1160);
            *(float2*)(orow + 1160) = t2;
        }
    } else {
        const float4* s4 = (const float4*)(srow + 2);        // +8B -> 16B aligned
        float4* o4 = (float4*)(orow + 2);
        o4[tid] = s4[tid];
        if (tid < 34) o4[256 + tid] = s4[256 + tid];        // floats 2..1161
        if (tid == 255) {                                    // head: floats 0,1
            float2 h2 = *(const float2*)srow;
            *(float2*)orow = h2;
        }
    }
    __syncthreads();

    // measure [0,256): masked iff c < th
    if (tid < sp[5]) orow[tid] = NEGF;
    // beat [256,272): threads 0..15
    if (tid < 16) {
        if (tid < sp[6] || tid >= sp[7]) orow[256 + tid] = NEGF;
    }
    // position [272,400): threads 128..255
    if (tid >= 128) {
        int pp = tid - 128;
        if (pp < sp[8]) orow[272 + pp] = NEGF;
    }
    // instrument [784,913): threads 0..128
    if (tid <= 128) {
        int im = sp[9];
        if (im) {
            uint32_t w = (uint32_t)sp[tid >> 5];
            bool pres = (w >> (tid & 31)) & 1u;
            bool masked = (im == 1) ? !pres : pres;
            if (masked) orow[784 + tid] = NEGF;
        }
    }
    // tempo [1113,1162): threads 96..144
    if (tid >= 96 && tid < 145) {
        int m = sp[14];
        if (m) {
            int cp = tid - 96;
            bool masked = (m == 1) ? (cp != sp[15]) : (cp == sp[15]);
            if (masked) orow[1113 + cp] = NEGF;
        }
    }
    // key_sign [1041,1065): threads 160..183
    if (tid >= 160 && tid < 184) {
        int m = sp[10];
        if (m) {
            int ck = tid - 160;
            bool masked = (m == 1) ? (ck != sp[11]) : (ck == sp[11]);
            if (masked) orow[1041 + ck] = NEGF;
        }
    }
    // time_sign [1065,1113): threads 184..231
    if (tid >= 184 && tid < 232) {
        int m = sp[12];
        if (m) {
            int ct = tid - 184;
            bool masked = (m == 1) ? (ct != sp[13]) : (ct == sp[13]);
            if (masked) orow[1065 + ct] = NEGF;
        }
    }
}

extern "C" void kernel_launch(void* const* d_in, const int* in_sizes, int n_in,
                              void* d_out, int out_size) {
    const int* song = (const int*)d_in[0];
    const int* chosen = (const int*)d_in[1];
    const float* scores = (const float*)d_in[2];
    float* out = (float*)d_out;

    prefix_kernel<<<BB, 256>>>(song);
    params_kernel<<<SS, 256>>>(song, chosen, scores);
    apply_kernel<<<ROWS, 256>>>(scores, out);
}

// round 4
// speedup vs baseline: 1.8288x; 1.3203x over previous
#include <cuda_runtime.h>
#include <stdint.h>

#define BB 8
#define SS 2047
#define RT 1162
#define ROWS (BB * SS)
#define NEGF (-1e9f)
#define CH 128
#define NCH 16

// Chunk-local inclusive prefix per (b, j), padded to 2048 rows per batch.
// words 0..4 = instrument-present bitset (129 bits),
// word 5 = key_sign 0x80000000|last_idx, word 6 = time_sign same,
// word 7 = tempo last_idx (plain; default 0 matches jnp.argmax-of-zeros).
__device__ uint32_t g_prefix[(size_t)BB * 2048 * 8];
__device__ uint32_t g_agg[BB * NCH * 8];
__device__ uint32_t g_carry[BB * NCH * 8];

__constant__ int c_num[12] = {1, 2, 3, 4, 5, 6, 7, 8, 9, 10, 12, 16};

__device__ __forceinline__ uint32_t pmax(uint32_t a, uint32_t b) { return a > b ? a : b; }

// 128 blocks (8 batches x 16 chunks) x 128 threads, 1 element/thread.
__global__ __launch_bounds__(128) void scan_local(const int* __restrict__ song) {
    int b = blockIdx.x >> 4;
    int c = blockIdx.x & 15;
    int tid = threadIdx.x, lane = tid & 31, warp = tid >> 5;
    int j = c * CH + tid;

    uint32_t S[8] = {0, 0, 0, 0, 0, 0, 0, 0};
    if (j < SS) {
        const int* e = song + ((size_t)b * SS + j) * 11;
        int ty = e[0];
        if (ty == 1) {
            int v = e[6];
            S[v >> 5] |= 1u << (v & 31);
        } else if (ty == 4) {
            S[5] = 0x80000000u | (uint32_t)j;
        } else if (ty == 5) {
            S[6] = 0x80000000u | (uint32_t)j;
        } else if (ty == 6) {
            S[7] = (uint32_t)j;
        }
    }

    // warp-inclusive shuffle scan (combine is commutative: OR / max)
#pragma unroll
    for (int d = 1; d < 32; d <<= 1) {
        uint32_t o[8];
#pragma unroll
        for (int w = 0; w < 8; ++w) o[w] = __shfl_up_sync(0xffffffffu, S[w], d);
        if (lane >= d) {
            S[0] |= o[0]; S[1] |= o[1]; S[2] |= o[2]; S[3] |= o[3]; S[4] |= o[4];
            S[5] = pmax(S[5], o[5]); S[6] = pmax(S[6], o[6]); S[7] = pmax(S[7], o[7]);
        }
    }

    __shared__ uint32_t agg[4][8];
    if (lane == 31) {
#pragma unroll
        for (int w = 0; w < 8; ++w) agg[warp][w] = S[w];
    }
    __syncthreads();
#pragma unroll
    for (int w2 = 0; w2 < 3; ++w2) {
        if (warp > w2) {
            S[0] |= agg[w2][0]; S[1] |= agg[w2][1]; S[2] |= agg[w2][2];
            S[3] |= agg[w2][3]; S[4] |= agg[w2][4];
            S[5] = pmax(S[5], agg[w2][5]);
            S[6] = pmax(S[6], agg[w2][6]);
            S[7] = pmax(S[7], agg[w2][7]);
        }
    }

    if (j < SS) {
        uint4* dst = (uint4*)&g_prefix[((size_t)b * 2048 + j) * 8];
        dst[0] = make_uint4(S[0], S[1], S[2], S[3]);
        dst[1] = make_uint4(S[4], S[5], S[6], S[7]);
    }
    int lastt = (c == NCH - 1) ? (SS - 1 - c * CH) : (CH - 1);
    if (tid == lastt) {
        uint4* a = (uint4*)&g_agg[(b * NCH + c) * 8];
        a[0] = make_uint4(S[0], S[1], S[2], S[3]);
        a[1] = make_uint4(S[4], S[5], S[6], S[7]);
    }
}

// 1 block, 8 warps; warp w = batch w: exclusive scan over 16 chunk aggregates.
__global__ __launch_bounds__(256) void scan_carry() {
    int warp = threadIdx.x >> 5;
    int lane = threadIdx.x & 31;
    uint32_t S[8] = {0, 0, 0, 0, 0, 0, 0, 0};
    if (lane < 16) {
        const uint4* a = (const uint4*)&g_agg[(warp * NCH + lane) * 8];
        uint4 a0 = a[0], a1 = a[1];
        S[0] = a0.x; S[1] = a0.y; S[2] = a0.z; S[3] = a0.w;
        S[4] = a1.x; S[5] = a1.y; S[6] = a1.z; S[7] = a1.w;
    }
#pragma unroll
    for (int d = 1; d < 16; d <<= 1) {
        uint32_t o[8];
#pragma unroll
        for (int w = 0; w < 8; ++w) o[w] = __shfl_up_sync(0xffffffffu, S[w], d);
        if (lane >= d && lane < 16) {
            S[0] |= o[0]; S[1] |= o[1]; S[2] |= o[2]; S[3] |= o[3]; S[4] |= o[4];
            S[5] = pmax(S[5], o[5]); S[6] = pmax(S[6], o[6]); S[7] = pmax(S[7], o[7]);
        }
    }
    uint32_t E[8];
#pragma unroll
    for (int w = 0; w < 8; ++w) E[w] = __shfl_up_sync(0xffffffffu, S[w], 1);
    if (lane == 0) {
#pragma unroll
        for (int w = 0; w < 8; ++w) E[w] = 0;
    }
    if (lane < 16) {
        uint4* cdst = (uint4*)&g_carry[(warp * NCH + lane) * 8];
        cdst[0] = make_uint4(E[0], E[1], E[2], E[3]);
        cdst[1] = make_uint4(E[4], E[5], E[6], E[7]);
    }
}

// Block per row: warps 1-7 copy (float4), warp 0 computes argmaxes + params,
// then all threads do sparse -1e9 overwrites.
__global__ __launch_bounds__(256) void apply_kernel(const int* __restrict__ song,
                                                    const int* __restrict__ chosen,
                                                    const float* __restrict__ scores,
                                                    float* __restrict__ out) {
    int row = blockIdx.x;
    int b = row / SS;
    int i = row - b * SS;
    int tid = threadIdx.x;
    int lane = tid & 31;
    const float* srow = scores + (size_t)row * RT;
    float* orow = out + (size_t)row * RT;

    __shared__ int sp[16];

    if (tid >= 32) {
        int t = tid - 32;   // 0..223
        if ((row & 1) == 0) {
            const float4* s4 = (const float4*)srow;
            float4* o4 = (float4*)orow;
            o4[t] = s4[t];
            if (t < 66) o4[224 + t] = s4[224 + t];   // 290 float4 = floats 0..1159
            if (t == 223) *(float2*)(orow + 1160) = *(const float2*)(srow + 1160);
        } else {
            const float4* s4 = (const float4*)(srow + 2);   // +8B -> 16B aligned
            float4* o4 = (float4*)(orow + 2);
            o4[t] = s4[t];
            if (t < 66) o4[224 + t] = s4[224 + t];   // floats 2..1161
            if (t == 223) *(float2*)orow = *(const float2*)srow;
        }
    } else {
        // --- warp 0: measure argmax (first-index tiebreak = jnp.argmax) ---
        float bv = srow[lane];
        int bi = lane;
#pragma unroll
        for (int k = 1; k < 8; ++k) {
            float v = srow[lane + 32 * k];
            if (v > bv) { bv = v; bi = lane + 32 * k; }
        }
#pragma unroll
        for (int d = 16; d; d >>= 1) {
            float ov = __shfl_down_sync(0xffffffffu, bv, d);
            int oi = __shfl_down_sync(0xffffffffu, bi, d);
            if (ov > bv || (ov == bv && oi < bi)) { bv = ov; bi = oi; }
        }
        int pred_m = bi;   // valid on lane 0

        // --- beat argmax over scores[256:272] ---
        float bb = srow[256 + (lane & 15)];
        int bj = lane & 15;
#pragma unroll
        for (int d = 8; d; d >>= 1) {
            float ov = __shfl_down_sync(0xffffffffu, bb, d, 16);
            int oj = __shfl_down_sync(0xffffffffu, bj, d, 16);
            if (ov > bb || (ov == bb && oj < bj)) { bb = ov; bj = oj; }
        }
        int pred_b = bj;   // valid on lane 0

        if (lane == 0) {
            int jj = (i + 1 < SS) ? i + 1 : SS - 1;
            const uint4* PL = (const uint4*)&g_prefix[((size_t)b * 2048 + jj) * 8];
            uint4 p0 = PL[0], p1 = PL[1];
            int cc = jj >> 7;
            const uint4* CR = (const uint4*)&g_carry[((size_t)b * NCH + cc) * 8];
            uint4 c0 = CR[0], c1 = CR[1];
            uint32_t w0 = p0.x | c0.x, w1 = p0.y | c0.y, w2 = p0.z | c0.z;
            uint32_t w3 = p0.w | c0.w, w4 = p1.x | c1.x;
            uint32_t wk = pmax(p1.y, c1.y), wt = pmax(p1.z, c1.z), wp = pmax(p1.w, c1.w);

            int ksidx = (int)(wk & 0x7fffffffu);
            int tsidx = (int)(wt & 0x7fffffffu);
            bool has_ks = (wk >> 31) != 0;
            bool has_ts = (wt >> 31) != 0;
            int last_ks = song[(size_t)(b * SS + ksidx) * 11 + 8];
            int last_ts = song[(size_t)(b * SS + tsidx) * 11 + 9];
            int last_tp = song[(size_t)(b * SS + (int)wp) * 11 + 10];
            int max_beat = c_num[last_ts % 12];

            const int* si = song + (size_t)row * 11;
            int sm1 = si[1], sb2 = si[2], sp3 = si[3];
            int t = chosen[row];

            bool c1f = (pred_m == sm1);
            int min_beat = c1f ? sb2 : 0;
            bool c2f = c1f && (pred_b == min_beat);
            int min_pos = c2f ? sp3 : 0;
            int min_m46 = (sb2 == 0 && sp3 == 0) ? sm1 : sm1 + 1;
            bool has_inst = (w0 | w1 | w2 | w3 | w4) != 0;
            bool is3 = (t == 3);

            sp[0] = (int)w0; sp[1] = (int)w1; sp[2] = (int)w2;
            sp[3] = (int)w3; sp[4] = (int)w4;
            sp[5] = is3 ? sm1 : ((t >= 4 && t <= 6) ? min_m46 : 0);
            sp[6] = is3 ? min_beat : 0;
            sp[7] = is3 ? max_beat : 16;
            sp[8] = is3 ? min_pos : 0;
            sp[9] = is3 ? 1 : ((t == 1 && has_inst) ? 2 : 0);
            sp[10] = is3 ? 1 : ((t == 4 && has_ks) ? 2 : 0);
            sp[11] = last_ks;
            sp[12] = is3 ? 1 : ((t == 5 && has_ts) ? 2 : 0);
            sp[13] = last_ts;
            sp[14] = is3 ? 1 : ((t == 6) ? 2 : 0);
            sp[15] = last_tp;
        }
    }
    __syncthreads();

    // --- sparse overwrites ---
    // measure [0,256)
    if (tid < sp[5]) orow[tid] = NEGF;
    // beat [256,272): threads 0..15
    if (tid < 16) {
        if (tid < sp[6] || tid >= sp[7]) orow[256 + tid] = NEGF;
    }
    // position [272,400): threads 128..255
    if (tid >= 128) {
        int pp = tid - 128;
        if (pp < sp[8]) orow[272 + pp] = NEGF;
    }
    // instrument [784,913): threads 0..128
    if (tid <= 128) {
        int im = sp[9];
        if (im) {
            uint32_t w = (uint32_t)sp[tid >> 5];
            bool pres = (w >> (tid & 31)) & 1u;
            bool masked = (im == 1) ? !pres : pres;
            if (masked) orow[784 + tid] = NEGF;
        }
    }
    // tempo [1113,1162): threads 96..144
    if (tid >= 96 && tid < 145) {
        int m = sp[14];
        if (m) {
            int cp = tid - 96;
            bool masked = (m == 1) ? (cp != sp[15]) : (cp == sp[15]);
            if (masked) orow[1113 + cp] = NEGF;
        }
    }
    // key_sign [1041,1065): threads 160..183
    if (tid >= 160 && tid < 184) {
        int m = sp[10];
        if (m) {
            int ck = tid - 160;
            bool masked = (m == 1) ? (ck != sp[11]) : (ck == sp[11]);
            if (masked) orow[1041 + ck] = NEGF;
        }
    }
    // time_sign [1065,1113): threads 184..231
    if (tid >= 184 && tid < 232) {
        int m = sp[12];
        if (m) {
            int ct = tid - 184;
            bool masked = (m == 1) ? (ct != sp[13]) : (ct == sp[13]);
            if (masked) orow[1065 + ct] = NEGF;
        }
    }
}

extern "C" void kernel_launch(void* const* d_in, const int* in_sizes, int n_in,
                              void* d_out, int out_size) {
    const int* song = (const int*)d_in[0];
    const int* chosen = (const int*)d_in[1];
    const float* scores = (const float*)d_in[2];
    float* out = (float*)d_out;

    scan_local<<<BB * NCH, CH>>>(song);
    scan_carry<<<1, 256>>>();
    apply_kernel<<<ROWS, 256>>>(song, chosen, scores, out);
}

// round 5
// speedup vs baseline: 2.3624x; 1.2917x over previous
#include <cuda_runtime.h>
#include <stdint.h>

#define BB 8
#define SS 2047
#define RT 1162
#define ROWS (BB * SS)
#define NEGF (-1e9f)
#define CH 128
#define NCH 16

// Chunk-local inclusive prefix per (b, j), padded to 2048 rows per batch.
// words 0..4 = instrument-present bitset (129 bits),
// word 5 = key_sign:  flag<<31 | j<<8 | value   (max selects latest; value inline)
// word 6 = time_sign: same encoding
// word 7 = tempo:     j<<8 | value, element j==0 always seeds its value
//          (matches jnp.argmax-of-zeros -> song[b,0,feat] semantics).
__device__ uint32_t g_prefix[(size_t)BB * 2048 * 8];
__device__ uint32_t g_agg[BB * NCH * 8];
__device__ uint32_t g_carry[BB * NCH * 8];

__constant__ int c_num[12] = {1, 2, 3, 4, 5, 6, 7, 8, 9, 10, 12, 16};

__device__ __forceinline__ uint32_t pmax(uint32_t a, uint32_t b) { return a > b ? a : b; }

// 128 blocks (8 batches x 16 chunks) x 128 threads, 1 element/thread.
__global__ __launch_bounds__(128) void scan_local(const int* __restrict__ song) {
    int b = blockIdx.x >> 4;
    int c = blockIdx.x & 15;
    int tid = threadIdx.x, lane = tid & 31, warp = tid >> 5;
    int j = c * CH + tid;

    uint32_t S[8] = {0, 0, 0, 0, 0, 0, 0, 0};
    if (j < SS) {
        const int* e = song + ((size_t)b * SS + j) * 11;
        int ty = e[0];
        if (ty == 1) {
            int v = e[6];
            S[v >> 5] |= 1u << (v & 31);
        } else if (ty == 4) {
            S[5] = 0x80000000u | ((uint32_t)j << 8) | (uint32_t)e[8];
        } else if (ty == 5) {
            S[6] = 0x80000000u | ((uint32_t)j << 8) | (uint32_t)e[9];
        } else if (ty == 6) {
            S[7] = ((uint32_t)j << 8) | (uint32_t)e[10];
        }
        if (j == 0) {   // seed: no-match default is index 0 -> its value
            S[5] = pmax(S[5], (uint32_t)e[8]);
            S[6] = pmax(S[6], (uint32_t)e[9]);
            S[7] = pmax(S[7], (uint32_t)e[10]);
        }
    }

    // warp-inclusive shuffle scan (combine is commutative: OR / max)
#pragma unroll
    for (int d = 1; d < 32; d <<= 1) {
        uint32_t o[8];
#pragma unroll
        for (int w = 0; w < 8; ++w) o[w] = __shfl_up_sync(0xffffffffu, S[w], d);
        if (lane >= d) {
            S[0] |= o[0]; S[1] |= o[1]; S[2] |= o[2]; S[3] |= o[3]; S[4] |= o[4];
            S[5] = pmax(S[5], o[5]); S[6] = pmax(S[6], o[6]); S[7] = pmax(S[7], o[7]);
        }
    }

    __shared__ uint32_t agg[4][8];
    if (lane == 31) {
#pragma unroll
        for (int w = 0; w < 8; ++w) agg[warp][w] = S[w];
    }
    __syncthreads();
#pragma unroll
    for (int w2 = 0; w2 < 3; ++w2) {
        if (warp > w2) {
            S[0] |= agg[w2][0]; S[1] |= agg[w2][1]; S[2] |= agg[w2][2];
            S[3] |= agg[w2][3]; S[4] |= agg[w2][4];
            S[5] = pmax(S[5], agg[w2][5]);
            S[6] = pmax(S[6], agg[w2][6]);
            S[7] = pmax(S[7], agg[w2][7]);
        }
    }

    if (j < SS) {
        uint4* dst = (uint4*)&g_prefix[((size_t)b * 2048 + j) * 8];
        dst[0] = make_uint4(S[0], S[1], S[2], S[3]);
        dst[1] = make_uint4(S[4], S[5], S[6], S[7]);
    }
    int lastt = (c == NCH - 1) ? (SS - 1 - c * CH) : (CH - 1);
    if (tid == lastt) {
        uint4* a = (uint4*)&g_agg[(b * NCH + c) * 8];
        a[0] = make_uint4(S[0], S[1], S[2], S[3]);
        a[1] = make_uint4(S[4], S[5], S[6], S[7]);
    }
}

// 1 block, 8 warps; warp w = batch w: exclusive scan over 16 chunk aggregates.
__global__ __launch_bounds__(256) void scan_carry() {
    int warp = threadIdx.x >> 5;
    int lane = threadIdx.x & 31;
    uint32_t S[8] = {0, 0, 0, 0, 0, 0, 0, 0};
    if (lane < 16) {
        const uint4* a = (const uint4*)&g_agg[(warp * NCH + lane) * 8];
        uint4 a0 = a[0], a1 = a[1];
        S[0] = a0.x; S[1] = a0.y; S[2] = a0.z; S[3] = a0.w;
        S[4] = a1.x; S[5] = a1.y; S[6] = a1.z; S[7] = a1.w;
    }
#pragma unroll
    for (int d = 1; d < 16; d <<= 1) {
        uint32_t o[8];
#pragma unroll
        for (int w = 0; w < 8; ++w) o[w] = __shfl_up_sync(0xffffffffu, S[w], d);
        if (lane >= d && lane < 16) {
            S[0] |= o[0]; S[1] |= o[1]; S[2] |= o[2]; S[3] |= o[3]; S[4] |= o[4];
            S[5] = pmax(S[5], o[5]); S[6] = pmax(S[6], o[6]); S[7] = pmax(S[7], o[7]);
        }
    }
    uint32_t E[8];
#pragma unroll
    for (int w = 0; w < 8; ++w) E[w] = __shfl_up_sync(0xffffffffu, S[w], 1);
    if (lane == 0) {
#pragma unroll
        for (int w = 0; w < 8; ++w) E[w] = 0;
    }
    if (lane < 16) {
        uint4* cdst = (uint4*)&g_carry[(warp * NCH + lane) * 8];
        cdst[0] = make_uint4(E[0], E[1], E[2], E[3]);
        cdst[1] = make_uint4(E[4], E[5], E[6], E[7]);
    }
}

// Warp per row: argmax + params + float4 copy + sparse overwrites. No block barrier.
__global__ __launch_bounds__(256) void apply_kernel(const int* __restrict__ song,
                                                    const int* __restrict__ chosen,
                                                    const float* __restrict__ scores,
                                                    float* __restrict__ out) {
    int warp = threadIdx.x >> 5;
    int lane = threadIdx.x & 31;
    int row = blockIdx.x * 8 + warp;      // grid = 2047 -> 16376 rows exactly
    int b = row / SS;
    int i = row - b * SS;
    const float* srow = scores + (size_t)row * RT;
    float* orow = out + (size_t)row * RT;

    __shared__ int sp_all[8][16];
    int* sp = sp_all[warp];

    // --- measure argmax over scores[0:256] (first-index tiebreak = jnp.argmax) ---
    float bv = srow[lane];
    int bi = lane;
#pragma unroll
    for (int k = 1; k < 8; ++k) {
        float v = srow[lane + 32 * k];
        if (v > bv) { bv = v; bi = lane + 32 * k; }
    }
#pragma unroll
    for (int d = 16; d; d >>= 1) {
        float ov = __shfl_down_sync(0xffffffffu, bv, d);
        int oi = __shfl_down_sync(0xffffffffu, bi, d);
        if (ov > bv || (ov == bv && oi < bi)) { bv = ov; bi = oi; }
    }
    int pred_m = bi;   // valid on lane 0

    // --- beat argmax over scores[256:272] ---
    float bb = srow[256 + (lane & 15)];
    int bj = lane & 15;
#pragma unroll
    for (int d = 8; d; d >>= 1) {
        float ov = __shfl_down_sync(0xffffffffu, bb, d, 16);
        int oj = __shfl_down_sync(0xffffffffu, bj, d, 16);
        if (ov > bb || (ov == bb && oj < bj)) { bb = ov; bj = oj; }
    }
    int pred_b = bj;   // valid on lane 0

    if (lane == 0) {
        int jj = (i + 1 < SS) ? i + 1 : SS - 1;
        const uint4* PL = (const uint4*)&g_prefix[((size_t)b * 2048 + jj) * 8];
        uint4 p0 = PL[0], p1 = PL[1];
        const uint4* CR = (const uint4*)&g_carry[((size_t)b * NCH + (jj >> 7)) * 8];
        uint4 c0 = CR[0], c1 = CR[1];
        uint32_t w0 = p0.x | c0.x, w1 = p0.y | c0.y, w2 = p0.z | c0.z;
        uint32_t w3 = p0.w | c0.w, w4 = p1.x | c1.x;
        uint32_t wk = pmax(p1.y, c1.y), wt = pmax(p1.z, c1.z), wp = pmax(p1.w, c1.w);

        int last_ks = (int)(wk & 0xffu);
        int last_ts = (int)(wt & 0xffu);
        int last_tp = (int)(wp & 0xffu);
        bool has_ks = (wk >> 31) != 0;
        bool has_ts = (wt >> 31) != 0;
        int max_beat = c_num[last_ts % 12];

        const int* si = song + (size_t)row * 11;
        int sm1 = si[1], sb2 = si[2], sp3 = si[3];
        int t = chosen[row];

        bool c1f = (pred_m == sm1);
        int min_beat = c1f ? sb2 : 0;
        bool c2f = c1f && (pred_b == min_beat);
        int min_pos = c2f ? sp3 : 0;
        int min_m46 = (sb2 == 0 && sp3 == 0) ? sm1 : sm1 + 1;
        bool has_inst = (w0 | w1 | w2 | w3 | w4) != 0;
        bool is3 = (t == 3);

        sp[0] = (int)w0; sp[1] = (int)w1; sp[2] = (int)w2;
        sp[3] = (int)w3; sp[4] = (int)w4;
        sp[5] = is3 ? sm1 : ((t >= 4 && t <= 6) ? min_m46 : 0);
        sp[6] = is3 ? min_beat : 0;
        sp[7] = is3 ? max_beat : 16;
        sp[8] = is3 ? min_pos : 0;
        sp[9] = is3 ? 1 : ((t == 1 && has_inst) ? 2 : 0);
        sp[10] = is3 ? 1 : ((t == 4 && has_ks) ? 2 : 0);
        sp[11] = last_ks;
        sp[12] = is3 ? 1 : ((t == 5 && has_ts) ? 2 : 0);
        sp[13] = last_ts;
        sp[14] = is3 ? 1 : ((t == 6) ? 2 : 0);
        sp[15] = last_tp;
    }

    // --- float4 copy (row byte offset = row*4648; 16B-aligned iff row even) ---
    if ((row & 1) == 0) {
        const float4* s4 = (const float4*)srow;
        float4* o4 = (float4*)orow;
#pragma unroll
        for (int p = lane; p < 290; p += 32) o4[p] = s4[p];    // floats 0..1159
        if (lane == 0) *(float2*)(orow + 1160) = *(const float2*)(srow + 1160);
    } else {
        const float4* s4 = (const float4*)(srow + 2);
        float4* o4 = (float4*)(orow + 2);
#pragma unroll
        for (int p = lane; p < 290; p += 32) o4[p] = s4[p];    // floats 2..1161
        if (lane == 0) *(float2*)orow = *(const float2*)srow;
    }
    __syncwarp();

    // --- sparse overwrites (lane-strided) ---
    int mth = sp[5], blo = sp[6], bhi = sp[7], pth = sp[8];
    int imode = sp[9], kmode = sp[10], kval = sp[11];
    int tsm = sp[12], tsv = sp[13], tpm = sp[14], tpv = sp[15];

    for (int c = lane; c < mth; c += 32) orow[c] = NEGF;                 // measure
    if (lane < 16 && (lane < blo || lane >= bhi)) orow[256 + lane] = NEGF;  // beat
    for (int p = lane; p < pth; p += 32) orow[272 + p] = NEGF;           // position
    if (imode) {                                                          // instrument
#pragma unroll
        for (int k = 0; k < 5; ++k) {
            int ci = lane + 32 * k;
            if (ci < 129) {
                bool pres = ((uint32_t)sp[k] >> lane) & 1u;
                bool masked = (imode == 1) ? !pres : pres;
                if (masked) orow[784 + ci] = NEGF;
            }
        }
    }
    if (kmode && lane < 24) {                                             // key_sign
        bool masked = (kmode == 1) ? (lane != kval) : (lane == kval);
        if (masked) orow[1041 + lane] = NEGF;
    }
    if (tsm) {                                                            // time_sign
#pragma unroll
        for (int k = 0; k < 2; ++k) {
            int ct = lane + 32 * k;
            if (ct < 48) {
                bool masked = (tsm == 1) ? (ct != tsv) : (ct == tsv);
                if (masked) orow[1065 + ct] = NEGF;
            }
        }
    }
    if (tpm) {                                                            // tempo
#pragma unroll
        for (int k = 0; k < 2; ++k) {
            int cp = lane + 32 * k;
            if (cp < 49) {
                bool masked = (tpm == 1) ? (cp != tpv) : (cp == tpv);
                if (masked) orow[1113 + cp] = NEGF;
            }
        }
    }
}

extern "C" void kernel_launch(void* const* d_in, const int* in_sizes, int n_in,
                              void* d_out, int out_size) {
    const int* song = (const int*)d_in[0];
    const int* chosen = (const int*)d_in[1];
    const float* scores = (const float*)d_in[2];
    float* out = (float*)d_out;

    scan_local<<<BB * NCH, CH>>>(song);
    scan_carry<<<1, 256>>>();
    apply_kernel<<<ROWS / 8, 256>>>(song, chosen, scores, out);
}